// round 15
// baseline (speedup 1.0000x reference)
#include <cuda_runtime.h>
#include <cuda_fp16.h>
#include <cstdint>
#include <cstddef>

#define N_ROWS 65536
#define HID    1024
#define D_IN   512
#define NCTA   148

// ---------------- scratch (__device__ globals: the sanctioned mechanism) ----
__device__ __align__(128) __half  g_hX[(size_t)N_ROWS * D_IN];
__device__ __align__(128) __half  g_hA[(size_t)N_ROWS * HID];
__device__ __align__(128) __half  g_hB[(size_t)N_ROWS * HID];
__device__ __align__(128) float   g_bufF[(size_t)N_ROWS * HID];
__device__ __align__(128) __half  g_wh0[HID * D_IN];   // W0^T [1024][512]
__device__ __align__(128) __half  g_wh1[HID * HID];
__device__ __align__(128) __half  g_wh2[HID * HID];
__device__ __align__(128) __half  g_wh3[HID * HID];

// ---------------- helpers ---------------------------------------------------
__device__ __forceinline__ uint32_t smem_u32(const void* p) {
    uint32_t a;
    asm("{ .reg .u64 t; cvta.to.shared.u64 t, %1; cvt.u32.u64 %0, t; }"
        : "=r"(a) : "l"(p));
    return a;
}
__device__ __forceinline__ void ldsm_x4(uint32_t* d, uint32_t addr) {
    asm volatile("ldmatrix.sync.aligned.m8n8.x4.shared.b16 {%0,%1,%2,%3}, [%4];"
                 : "=r"(d[0]), "=r"(d[1]), "=r"(d[2]), "=r"(d[3]) : "r"(addr));
}
__device__ __forceinline__ void mma_f16(float* c, const uint32_t* a,
                                        uint32_t b0, uint32_t b1) {
    asm volatile(
        "mma.sync.aligned.m16n8k16.row.col.f32.f16.f16.f32 "
        "{%0,%1,%2,%3}, {%4,%5,%6,%7}, {%8,%9}, {%0,%1,%2,%3};"
        : "+f"(c[0]), "+f"(c[1]), "+f"(c[2]), "+f"(c[3])
        : "r"(a[0]), "r"(a[1]), "r"(a[2]), "r"(a[3]), "r"(b0), "r"(b1));
}
__device__ __forceinline__ void cp16(uint32_t dst, const void* src) {
    asm volatile("cp.async.cg.shared.global [%0], [%1], 16;" :: "r"(dst), "l"(src));
}

// ---------------------------------------------------------------------------
// Persistent fp16 mma.sync GEMM: C[65536,1024] = A[65536,K] @ Bt[1024,K]^T.
// BM=128, BN=256, BK=32; 512 threads (16 warps), warp tile 32x64.
// 148 persistent CTAs; each walks tiles bid, bid+148, ... The cp.async loader
// streams a GLOBAL chunk sequence (tile-major, k-minor) through 5 smem stages,
// so tile t+1's loads overlap tile t's tail MMAs and epilogue. Pipeline is
// filled once per CTA instead of once per tile.
// EPI=1: half out = rn(relu(acc+bias));  EPI=0: half out = rn(acc);
// EPI=2: fp32 raw out.
// ---------------------------------------------------------------------------
template<int K, int EPI>
__global__ __launch_bounds__(512, 1)
void gemm_h(const __half* __restrict__ A, const __half* __restrict__ Bt,
            const float* __restrict__ bias, void* __restrict__ Cout)
{
    constexpr int KT     = K / 32;                 // chunks per tile
    constexpr int LOG_KT = (K == 1024) ? 5 : 4;
    constexpr int STAGE  = 24576;                  // A 8K + B 16K
    constexpr int ST     = 5;
    constexpr int TILES  = (N_ROWS / 128) * (HID / 256);   // 2048

    extern __shared__ char smem[];
    const uint32_t sb = smem_u32(smem);

    const int tid  = threadIdx.x;
    const int lane = tid & 31, warp = tid >> 5;
    const int wm   = warp & 3;                  // 4 warps in m (32 rows each)
    const int wn   = warp >> 2;                 // 4 warps in n (64 cols each)
    const int bid  = blockIdx.x;
    const int ncta = gridDim.x;

    const int nt      = (TILES - bid + ncta - 1) / ncta;   // tiles for this CTA
    const int C_total = nt * KT;

    // ---- cp.async geometry ----
    const int ldr = tid >> 2;                   // 0..127
    const int ldc = tid & 3;                    // chunk 0..3
    const __half* Abase = A  + (size_t)ldr * K + ldc * 8;
    const __half* Bbase = Bt + (size_t)ldr * K + ldc * 8;

    const uint32_t offA = (uint32_t)(ldr * 64 + ((ldc ^ ((ldr >> 1) & 3)) * 16));
    const int rB1 = ldr + 128;
    const uint32_t offB0 = offA;
    const uint32_t offB1 = (uint32_t)(rB1 * 64 + ((ldc ^ ((rB1 >> 1) & 3)) * 16));

    auto load_chunk = [&](int c) {
        const int ti = c >> LOG_KT;
        const int kt = c & (KT - 1);
        const int tl = bid + ti * ncta;
        const int lm0 = (tl >> 2) << 7;
        const int ln0 = (tl & 3) << 8;
        const uint32_t st = sb + (uint32_t)(c % ST) * STAGE;
        const __half* ag = Abase + (size_t)lm0 * K + kt * 32;
        const __half* bg = Bbase + (size_t)ln0 * K + kt * 32;
        cp16(st + offA,         ag);
        cp16(st + 8192 + offB0, bg);
        cp16(st + 8192 + offB1, bg + (size_t)128 * K);
        asm volatile("cp.async.commit_group;" ::: "memory");
    };

    // ---- ldmatrix per-thread geometry ----
    const uint32_t ArowL = (uint32_t)(wm * 32 + (lane & 15));
    const uint32_t hiA   = (uint32_t)(lane >> 4);
    const uint32_t BrowL = (uint32_t)(wn * 64 + (lane & 7) + ((lane >> 4) << 3));
    const uint32_t hiB   = (uint32_t)((lane >> 3) & 1);

    float acc[2][8][4];
#pragma unroll
    for (int i = 0; i < 2; i++)
#pragma unroll
        for (int j = 0; j < 8; j++)
#pragma unroll
            for (int q = 0; q < 4; q++) acc[i][j][q] = 0.f;

    load_chunk(0); load_chunk(1); load_chunk(2); load_chunk(3);

    int tile = bid;
    int m0 = (tile >> 2) << 7;
    int n0 = (tile & 3) << 8;

    for (int c = 0; c < C_total; c++) {
        const int rem = C_total - 1 - c;
        if (rem >= 3)      asm volatile("cp.async.wait_group 3;" ::: "memory");
        else if (rem == 2) asm volatile("cp.async.wait_group 2;" ::: "memory");
        else if (rem == 1) asm volatile("cp.async.wait_group 1;" ::: "memory");
        else               asm volatile("cp.async.wait_group 0;" ::: "memory");
        __syncthreads();
        if (c + 4 < C_total) load_chunk(c + 4);

        const uint32_t stA = sb + (uint32_t)(c % ST) * STAGE;
        const uint32_t stB = stA + 8192;

#pragma unroll
        for (int ks = 0; ks < 2; ks++) {
            uint32_t a[2][4];
#pragma unroll
            for (int mi = 0; mi < 2; mi++) {
                const uint32_t r = ArowL + mi * 16;
                const uint32_t kc = (uint32_t)(ks * 2) + hiA;
                ldsm_x4(a[mi], stA + r * 64 + ((kc ^ ((r >> 1) & 3)) * 16));
            }
            uint32_t b[4][4];
#pragma unroll
            for (int np = 0; np < 4; np++) {
                const uint32_t r = BrowL + np * 16;
                const uint32_t kc = (uint32_t)(ks * 2) + hiB;
                ldsm_x4(b[np], stB + r * 64 + ((kc ^ ((r >> 1) & 3)) * 16));
            }
#pragma unroll
            for (int mi = 0; mi < 2; mi++)
#pragma unroll
                for (int ni = 0; ni < 8; ni++)
                    mma_f16(acc[mi][ni], a[mi],
                            b[ni >> 1][(ni & 1) * 2], b[ni >> 1][(ni & 1) * 2 + 1]);
        }

        // ---- tile boundary: epilogue (overlaps next tile's in-flight loads) --
        if ((c & (KT - 1)) == KT - 1) {
#pragma unroll
            for (int mi = 0; mi < 2; mi++) {
                const int r = m0 + wm * 32 + mi * 16 + (lane >> 2);
#pragma unroll
                for (int ni = 0; ni < 8; ni++) {
                    const int col = n0 + wn * 64 + ni * 8 + (lane & 3) * 2;
                    float c0 = acc[mi][ni][0], c1 = acc[mi][ni][1];
                    float c2 = acc[mi][ni][2], c3 = acc[mi][ni][3];
                    if (EPI == 1) {
                        __half* C = (__half*)Cout;
                        const float b0v = bias[col], b1v = bias[col + 1];
                        *(__half2*)(C + (size_t)r * HID + col) =
                            __floats2half2_rn(fmaxf(c0 + b0v, 0.f), fmaxf(c1 + b1v, 0.f));
                        *(__half2*)(C + (size_t)(r + 8) * HID + col) =
                            __floats2half2_rn(fmaxf(c2 + b0v, 0.f), fmaxf(c3 + b1v, 0.f));
                    } else if (EPI == 0) {
                        __half* C = (__half*)Cout;
                        *(__half2*)(C + (size_t)r * HID + col) =
                            __floats2half2_rn(c0, c1);
                        *(__half2*)(C + (size_t)(r + 8) * HID + col) =
                            __floats2half2_rn(c2, c3);
                    } else {
                        float* C = (float*)Cout;
                        *(float2*)(C + (size_t)r * HID + col)       = make_float2(c0, c1);
                        *(float2*)(C + (size_t)(r + 8) * HID + col) = make_float2(c2, c3);
                    }
#pragma unroll
                    for (int q = 0; q < 4; q++) acc[mi][ni][q] = 0.f;
                }
            }
            tile += ncta;
            m0 = (tile >> 2) << 7;
            n0 = (tile & 3) << 8;
        }
    }
}

// ---------------------------------------------------------------------------
// Round-copy fp32 -> fp16 (rn): for raw input X.
// ---------------------------------------------------------------------------
__global__ __launch_bounds__(256)
void round_copy_h(const float* __restrict__ in, __half* __restrict__ out)
{
    const size_t i = ((size_t)blockIdx.x * 256 + threadIdx.x) * 4;
    float4 v = *(const float4*)(in + i);
    *(__half2*)(out + i)     = __floats2half2_rn(v.x, v.y);
    *(__half2*)(out + i + 2) = __floats2half2_rn(v.z, v.w);
}

// ---------------------------------------------------------------------------
// Weight transpose + fp16 round: out[n*R + r] = half_rn(in[r*C + n])
// ---------------------------------------------------------------------------
__global__ __launch_bounds__(256)
void transpose_h(const float* __restrict__ in, __half* __restrict__ out,
                 int R, int C)
{
    __shared__ float t[32][33];
    const int c0 = blockIdx.x * 32, r0 = blockIdx.y * 32;
    const int x = threadIdx.x, y = threadIdx.y;
#pragma unroll
    for (int i = 0; i < 32; i += 8)
        t[y + i][x] = in[(size_t)(r0 + y + i) * C + c0 + x];
    __syncthreads();
#pragma unroll
    for (int i = 0; i < 32; i += 8)
        out[(size_t)(c0 + y + i) * R + r0 + x] = __float2half_rn(t[x][y + i]);
}

// ---------------------------------------------------------------------------
// LayerNorm over half input -> half output. Stats in fp32 from half values.
// ---------------------------------------------------------------------------
__global__ __launch_bounds__(256)
void ln_relu_hh(const __half* __restrict__ H, const float* __restrict__ g,
                const float* __restrict__ be, __half* __restrict__ O)
{
    const int row = blockIdx.x;
    const int tid = threadIdx.x;
    const __half2* p = (const __half2*)(H + (size_t)row * 1024) + tid * 2;
    const float2 f0 = __half22float2(p[0]);
    const float2 f1 = __half22float2(p[1]);

    float s  = f0.x + f0.y + f1.x + f1.y;
    float sq = f0.x * f0.x + f0.y * f0.y + f1.x * f1.x + f1.y * f1.y;

    __shared__ float ss[8], ssq[8];
    const int lane = tid & 31, warp = tid >> 5;
#pragma unroll
    for (int o = 16; o > 0; o >>= 1) {
        s  += __shfl_down_sync(0xffffffffu, s,  o);
        sq += __shfl_down_sync(0xffffffffu, sq, o);
    }
    if (lane == 0) { ss[warp] = s; ssq[warp] = sq; }
    __syncthreads();
    if (warp == 0) {
        s  = (lane < 8) ? ss[lane]  : 0.f;
        sq = (lane < 8) ? ssq[lane] : 0.f;
#pragma unroll
        for (int o = 4; o > 0; o >>= 1) {
            s  += __shfl_down_sync(0xffffffffu, s,  o);
            sq += __shfl_down_sync(0xffffffffu, sq, o);
        }
        if (lane == 0) { ss[0] = s; ssq[0] = sq; }
    }
    __syncthreads();

    const float mean = ss[0] * (1.0f / 1024.0f);
    const float var  = ssq[0] * (1.0f / 1024.0f) - mean * mean;
    const float rstd = rsqrtf(var + 1e-6f);

    const float4 gv = ((const float4*)g)[tid];
    const float4 bv = ((const float4*)be)[tid];
    const float ox = fmaxf(fmaf((f0.x - mean) * rstd, gv.x, bv.x), 0.f);
    const float oy = fmaxf(fmaf((f0.y - mean) * rstd, gv.y, bv.y), 0.f);
    const float oz = fmaxf(fmaf((f1.x - mean) * rstd, gv.z, bv.z), 0.f);
    const float ow = fmaxf(fmaf((f1.y - mean) * rstd, gv.w, bv.w), 0.f);

    __half2* op = (__half2*)(O + (size_t)row * 1024) + tid * 2;
    op[0] = __floats2half2_rn(ox, oy);
    op[1] = __floats2half2_rn(oz, ow);
}

// ---------------------------------------------------------------------------
// Final fused: LayerNorm (exact, fp32 in) + ReLU + dot(Wout) + bias + ReLU.
// ---------------------------------------------------------------------------
__global__ __launch_bounds__(256)
void ln_dot(const float* __restrict__ H, const float* __restrict__ g,
            const float* __restrict__ be, const float* __restrict__ Wout,
            const float* __restrict__ bout, float* __restrict__ out)
{
    const int row = blockIdx.x;
    const int tid = threadIdx.x;
    const float4 v = ((const float4*)(H + (size_t)row * 1024))[tid];
    float s  = v.x + v.y + v.z + v.w;
    float sq = v.x * v.x + v.y * v.y + v.z * v.z + v.w * v.w;

    __shared__ float ss[8], ssq[8];
    const int lane = tid & 31, warp = tid >> 5;
#pragma unroll
    for (int o = 16; o > 0; o >>= 1) {
        s  += __shfl_down_sync(0xffffffffu, s,  o);
        sq += __shfl_down_sync(0xffffffffu, sq, o);
    }
    if (lane == 0) { ss[warp] = s; ssq[warp] = sq; }
    __syncthreads();
    if (warp == 0) {
        s  = (lane < 8) ? ss[lane]  : 0.f;
        sq = (lane < 8) ? ssq[lane] : 0.f;
#pragma unroll
        for (int o = 4; o > 0; o >>= 1) {
            s  += __shfl_down_sync(0xffffffffu, s,  o);
            sq += __shfl_down_sync(0xffffffffu, sq, o);
        }
        if (lane == 0) { ss[0] = s; ssq[0] = sq; }
    }
    __syncthreads();

    const float mean = ss[0] * (1.0f / 1024.0f);
    const float var  = ssq[0] * (1.0f / 1024.0f) - mean * mean;
    const float rstd = rsqrtf(var + 1e-6f);

    const float4 gv = ((const float4*)g)[tid];
    const float4 bv = ((const float4*)be)[tid];
    const float4 wv = ((const float4*)Wout)[tid];
    float d = 0.f;
    d = fmaf(fmaxf(fmaf((v.x - mean) * rstd, gv.x, bv.x), 0.f), wv.x, d);
    d = fmaf(fmaxf(fmaf((v.y - mean) * rstd, gv.y, bv.y), 0.f), wv.y, d);
    d = fmaf(fmaxf(fmaf((v.z - mean) * rstd, gv.z, bv.z), 0.f), wv.z, d);
    d = fmaf(fmaxf(fmaf((v.w - mean) * rstd, gv.w, bv.w), 0.f), wv.w, d);

#pragma unroll
    for (int o = 16; o > 0; o >>= 1) d += __shfl_down_sync(0xffffffffu, d, o);
    if (lane == 0) ss[warp] = d;
    __syncthreads();
    if (tid == 0) {
        float t = 0.f;
#pragma unroll
        for (int w = 0; w < 8; w++) t += ss[w];
        out[row] = fmaxf(t + bout[0], 0.f);
    }
}

// ---------------------------------------------------------------------------
extern "C" void kernel_launch(void* const* d_in, const int* in_sizes, int n_in,
                              void* d_out, int out_size)
{
    const float* X    = (const float*)d_in[0];
    const float* W0   = (const float*)d_in[1];
    const float* b0   = (const float*)d_in[2];
    const float* W1   = (const float*)d_in[3];
    const float* g1   = (const float*)d_in[4];
    const float* be1  = (const float*)d_in[5];
    const float* W2   = (const float*)d_in[6];
    const float* g2   = (const float*)d_in[7];
    const float* be2  = (const float*)d_in[8];
    const float* W3   = (const float*)d_in[9];
    const float* g3   = (const float*)d_in[10];
    const float* be3  = (const float*)d_in[11];
    const float* Wout = (const float*)d_in[12];
    const float* bout = (const float*)d_in[13];
    float* out = (float*)d_out;

    __half *hX, *hA, *hB, *wh0, *wh1, *wh2, *wh3;
    float* bufF;
    cudaGetSymbolAddress((void**)&hX,  g_hX);
    cudaGetSymbolAddress((void**)&hA,  g_hA);
    cudaGetSymbolAddress((void**)&hB,  g_hB);
    cudaGetSymbolAddress((void**)&bufF, g_bufF);
    cudaGetSymbolAddress((void**)&wh0, g_wh0);
    cudaGetSymbolAddress((void**)&wh1, g_wh1);
    cudaGetSymbolAddress((void**)&wh2, g_wh2);
    cudaGetSymbolAddress((void**)&wh3, g_wh3);

    constexpr int SMEM_REQ = 5 * 24576;   // 120 KB
    cudaFuncSetAttribute(gemm_h<D_IN, 1>,
                         cudaFuncAttributeMaxDynamicSharedMemorySize, SMEM_REQ);
    cudaFuncSetAttribute(gemm_h<HID, 0>,
                         cudaFuncAttributeMaxDynamicSharedMemorySize, SMEM_REQ);
    cudaFuncSetAttribute(gemm_h<HID, 2>,
                         cudaFuncAttributeMaxDynamicSharedMemorySize, SMEM_REQ);

    // prep: round X to fp16; transpose + round weights
    round_copy_h<<<(N_ROWS * D_IN) / (256 * 4), 256>>>(X, hX);
    transpose_h<<<dim3(HID / 32, D_IN / 32), dim3(32, 8)>>>(W0, wh0, D_IN, HID);
    transpose_h<<<dim3(HID / 32, HID / 32), dim3(32, 8)>>>(W1, wh1, HID, HID);
    transpose_h<<<dim3(HID / 32, HID / 32), dim3(32, 8)>>>(W2, wh2, HID, HID);
    transpose_h<<<dim3(HID / 32, HID / 32), dim3(32, 8)>>>(W3, wh3, HID, HID);

    // layer 0: Dense + bias + relu -> half
    gemm_h<D_IN, 1><<<NCTA, 512, SMEM_REQ>>>(hX, wh0, b0, hA);

    // layers 1-2: Dense -> half raw; LN(stats from half) + relu -> half
    gemm_h<HID, 0><<<NCTA, 512, SMEM_REQ>>>(hA, wh1, nullptr, hB);
    ln_relu_hh<<<N_ROWS, 256>>>(hB, g1, be1, hA);

    gemm_h<HID, 0><<<NCTA, 512, SMEM_REQ>>>(hA, wh2, nullptr, hB);
    ln_relu_hh<<<N_ROWS, 256>>>(hB, g2, be2, hA);

    // layer 3: Dense -> fp32 raw (exact final LN)
    gemm_h<HID, 2><<<NCTA, 512, SMEM_REQ>>>(hA, wh3, nullptr, bufF);

    // final: LN + relu + Dense(1) + relu, fused
    ln_dot<<<N_ROWS, 256>>>(bufF, g3, be3, Wout, bout, out);
}

// round 16
// speedup vs baseline: 1.2615x; 1.2615x over previous
#include <cuda_runtime.h>
#include <cuda_fp16.h>
#include <cstdint>
#include <cstddef>

#define N_ROWS 65536
#define HID    1024
#define D_IN   512

// ---------------- scratch (__device__ globals: the sanctioned mechanism) ----
__device__ __align__(128) __half  g_hX[(size_t)N_ROWS * D_IN];
__device__ __align__(128) __half  g_hA[(size_t)N_ROWS * HID];
__device__ __align__(128) __half  g_hB[(size_t)N_ROWS * HID];
__device__ __align__(128) __half  g_wh0[HID * D_IN];   // W0^T [1024][512]
__device__ __align__(128) __half  g_wh1[HID * HID];
__device__ __align__(128) __half  g_wh2[HID * HID];
__device__ __align__(128) __half  g_wh3[HID * HID];

// ---------------- helpers ---------------------------------------------------
__device__ __forceinline__ uint32_t smem_u32(const void* p) {
    uint32_t a;
    asm("{ .reg .u64 t; cvta.to.shared.u64 t, %1; cvt.u32.u64 %0, t; }"
        : "=r"(a) : "l"(p));
    return a;
}
__device__ __forceinline__ void ldsm_x4(uint32_t* d, uint32_t addr) {
    asm volatile("ldmatrix.sync.aligned.m8n8.x4.shared.b16 {%0,%1,%2,%3}, [%4];"
                 : "=r"(d[0]), "=r"(d[1]), "=r"(d[2]), "=r"(d[3]) : "r"(addr));
}
__device__ __forceinline__ void mma_f16(float* c, const uint32_t* a,
                                        uint32_t b0, uint32_t b1) {
    asm volatile(
        "mma.sync.aligned.m16n8k16.row.col.f32.f16.f16.f32 "
        "{%0,%1,%2,%3}, {%4,%5,%6,%7}, {%8,%9}, {%0,%1,%2,%3};"
        : "+f"(c[0]), "+f"(c[1]), "+f"(c[2]), "+f"(c[3])
        : "r"(a[0]), "r"(a[1]), "r"(a[2]), "r"(a[3]), "r"(b0), "r"(b1));
}
__device__ __forceinline__ void cp16(uint32_t dst, const void* src) {
    asm volatile("cp.async.cg.shared.global [%0], [%1], 16;" :: "r"(dst), "l"(src));
}
__device__ __forceinline__ void stcs_h2(__half2* p, __half2 v) {
    asm volatile("st.global.cs.b32 [%0], %1;" :: "l"(p), "r"(*(uint32_t*)&v));
}

// ---------------------------------------------------------------------------
// fp16 mma.sync GEMM: C[M,1024] = A[M,K] @ Bt[1024,K]^T  (fp32 accum)
// BM=128, BN=256, BK=32, 5-stage cp.async pipeline, 512 threads (16 warps),
// warp tile 32x64 (m16n8k16). 64B rows; 16B-chunk XOR swizzle.
// EPI=1: half out = rn(relu(acc+bias));  EPI=0: half out = rn(acc).
// Streaming (cs) epilogue stores: output is consumed exactly once.
// ---------------------------------------------------------------------------
template<int K, int EPI>
__global__ __launch_bounds__(512, 1)
void gemm_h(const __half* __restrict__ A, const __half* __restrict__ Bt,
            const float* __restrict__ bias, __half* __restrict__ C)
{
    constexpr int KT = K / 32;
    constexpr int STAGE = 24576;               // A 8K + B 16K
    constexpr int ST = 5;

    extern __shared__ char smem[];
    const uint32_t sb = smem_u32(smem);

    const int tid  = threadIdx.x;
    const int lane = tid & 31, warp = tid >> 5;
    const int wm   = warp & 3;                  // 4 warps in m (32 rows each)
    const int wn   = warp >> 2;                 // 4 warps in n (64 cols each)
    const int m0   = blockIdx.y * 128;
    const int n0   = blockIdx.x * 256;

    // ---- cp.async geometry ----
    const int ldr = tid >> 2;                   // 0..127
    const int ldc = tid & 3;                    // chunk 0..3
    const __half* Ag = A  + (size_t)(m0 + ldr) * K + ldc * 8;
    const __half* Bg = Bt + (size_t)(n0 + ldr) * K + ldc * 8;

    const uint32_t offA = (uint32_t)(ldr * 64 + ((ldc ^ ((ldr >> 1) & 3)) * 16));
    const int rB1 = ldr + 128;
    const uint32_t offB0 = offA;
    const uint32_t offB1 = (uint32_t)(rB1 * 64 + ((ldc ^ ((rB1 >> 1) & 3)) * 16));

    auto load_tile = [&](int kt) {
        const uint32_t st = sb + (uint32_t)(kt % ST) * STAGE;
        const __half* ag = Ag + kt * 32;
        const __half* bg = Bg + kt * 32;
        cp16(st + offA,         ag);
        cp16(st + 8192 + offB0, bg);
        cp16(st + 8192 + offB1, bg + (size_t)128 * K);
        asm volatile("cp.async.commit_group;" ::: "memory");
    };

    // ---- ldmatrix per-thread geometry ----
    const uint32_t ArowL = (uint32_t)(wm * 32 + (lane & 15));
    const uint32_t hiA   = (uint32_t)(lane >> 4);
    const uint32_t BrowL = (uint32_t)(wn * 64 + (lane & 7) + ((lane >> 4) << 3));
    const uint32_t hiB   = (uint32_t)((lane >> 3) & 1);

    float acc[2][8][4];
#pragma unroll
    for (int i = 0; i < 2; i++)
#pragma unroll
        for (int j = 0; j < 8; j++)
#pragma unroll
            for (int q = 0; q < 4; q++) acc[i][j][q] = 0.f;

    load_tile(0); load_tile(1); load_tile(2); load_tile(3);

    for (int kt = 0; kt < KT; kt++) {
        if (kt + 4 <= KT)      asm volatile("cp.async.wait_group 3;" ::: "memory");
        else if (kt + 3 == KT) asm volatile("cp.async.wait_group 2;" ::: "memory");
        else if (kt + 2 == KT) asm volatile("cp.async.wait_group 1;" ::: "memory");
        else                   asm volatile("cp.async.wait_group 0;" ::: "memory");
        __syncthreads();
        if (kt + 4 < KT) load_tile(kt + 4);

        const uint32_t stA = sb + (uint32_t)(kt % ST) * STAGE;
        const uint32_t stB = stA + 8192;

#pragma unroll
        for (int ks = 0; ks < 2; ks++) {
            uint32_t a[2][4];
#pragma unroll
            for (int mi = 0; mi < 2; mi++) {
                const uint32_t r = ArowL + mi * 16;
                const uint32_t kc = (uint32_t)(ks * 2) + hiA;
                ldsm_x4(a[mi], stA + r * 64 + ((kc ^ ((r >> 1) & 3)) * 16));
            }
            uint32_t b[4][4];
#pragma unroll
            for (int np = 0; np < 4; np++) {
                const uint32_t r = BrowL + np * 16;
                const uint32_t kc = (uint32_t)(ks * 2) + hiB;
                ldsm_x4(b[np], stB + r * 64 + ((kc ^ ((r >> 1) & 3)) * 16));
            }
#pragma unroll
            for (int mi = 0; mi < 2; mi++)
#pragma unroll
                for (int ni = 0; ni < 8; ni++)
                    mma_f16(acc[mi][ni], a[mi],
                            b[ni >> 1][(ni & 1) * 2], b[ni >> 1][(ni & 1) * 2 + 1]);
        }
    }

    // ---- epilogue (streaming stores) ----
#pragma unroll
    for (int mi = 0; mi < 2; mi++) {
        const int r = m0 + wm * 32 + mi * 16 + (lane >> 2);
#pragma unroll
        for (int ni = 0; ni < 8; ni++) {
            const int col = n0 + wn * 64 + ni * 8 + (lane & 3) * 2;
            float c0 = acc[mi][ni][0], c1 = acc[mi][ni][1];
            float c2 = acc[mi][ni][2], c3 = acc[mi][ni][3];
            if (EPI == 1) {
                const float b0v = bias[col], b1v = bias[col + 1];
                c0 = fmaxf(c0 + b0v, 0.f); c1 = fmaxf(c1 + b1v, 0.f);
                c2 = fmaxf(c2 + b0v, 0.f); c3 = fmaxf(c3 + b1v, 0.f);
            }
            stcs_h2((__half2*)(C + (size_t)r * HID + col),       __floats2half2_rn(c0, c1));
            stcs_h2((__half2*)(C + (size_t)(r + 8) * HID + col), __floats2half2_rn(c2, c3));
        }
    }
}

// ---------------------------------------------------------------------------
// Round-copy fp32 -> fp16 (rn): for raw input X.
// ---------------------------------------------------------------------------
__global__ __launch_bounds__(256)
void round_copy_h(const float* __restrict__ in, __half* __restrict__ out)
{
    const size_t i = ((size_t)blockIdx.x * 256 + threadIdx.x) * 4;
    float4 v = *(const float4*)(in + i);
    *(__half2*)(out + i)     = __floats2half2_rn(v.x, v.y);
    *(__half2*)(out + i + 2) = __floats2half2_rn(v.z, v.w);
}

// ---------------------------------------------------------------------------
// Weight transpose + fp16 round: out[n*R + r] = half_rn(in[r*C + n])
// ---------------------------------------------------------------------------
__global__ __launch_bounds__(256)
void transpose_h(const float* __restrict__ in, __half* __restrict__ out,
                 int R, int C)
{
    __shared__ float t[32][33];
    const int c0 = blockIdx.x * 32, r0 = blockIdx.y * 32;
    const int x = threadIdx.x, y = threadIdx.y;
#pragma unroll
    for (int i = 0; i < 32; i += 8)
        t[y + i][x] = in[(size_t)(r0 + y + i) * C + c0 + x];
    __syncthreads();
#pragma unroll
    for (int i = 0; i < 32; i += 8)
        out[(size_t)(c0 + y + i) * R + r0 + x] = __float2half_rn(t[x][y + i]);
}

// ---------------------------------------------------------------------------
// LayerNorm over half input -> half output. Stats in fp32 from half values.
// ---------------------------------------------------------------------------
__global__ __launch_bounds__(256)
void ln_relu_hh(const __half* __restrict__ H, const float* __restrict__ g,
                const float* __restrict__ be, __half* __restrict__ O)
{
    const int row = blockIdx.x;
    const int tid = threadIdx.x;
    const __half2* p = (const __half2*)(H + (size_t)row * 1024) + tid * 2;
    const float2 f0 = __half22float2(p[0]);
    const float2 f1 = __half22float2(p[1]);

    float s  = f0.x + f0.y + f1.x + f1.y;
    float sq = f0.x * f0.x + f0.y * f0.y + f1.x * f1.x + f1.y * f1.y;

    __shared__ float ss[8], ssq[8];
    const int lane = tid & 31, warp = tid >> 5;
#pragma unroll
    for (int o = 16; o > 0; o >>= 1) {
        s  += __shfl_down_sync(0xffffffffu, s,  o);
        sq += __shfl_down_sync(0xffffffffu, sq, o);
    }
    if (lane == 0) { ss[warp] = s; ssq[warp] = sq; }
    __syncthreads();
    if (warp == 0) {
        s  = (lane < 8) ? ss[lane]  : 0.f;
        sq = (lane < 8) ? ssq[lane] : 0.f;
#pragma unroll
        for (int o = 4; o > 0; o >>= 1) {
            s  += __shfl_down_sync(0xffffffffu, s,  o);
            sq += __shfl_down_sync(0xffffffffu, sq, o);
        }
        if (lane == 0) { ss[0] = s; ssq[0] = sq; }
    }
    __syncthreads();

    const float mean = ss[0] * (1.0f / 1024.0f);
    const float var  = ssq[0] * (1.0f / 1024.0f) - mean * mean;
    const float rstd = rsqrtf(var + 1e-6f);

    const float4 gv = ((const float4*)g)[tid];
    const float4 bv = ((const float4*)be)[tid];
    const float ox = fmaxf(fmaf((f0.x - mean) * rstd, gv.x, bv.x), 0.f);
    const float oy = fmaxf(fmaf((f0.y - mean) * rstd, gv.y, bv.y), 0.f);
    const float oz = fmaxf(fmaf((f1.x - mean) * rstd, gv.z, bv.z), 0.f);
    const float ow = fmaxf(fmaf((f1.y - mean) * rstd, gv.w, bv.w), 0.f);

    __half2* op = (__half2*)(O + (size_t)row * 1024) + tid * 2;
    op[0] = __floats2half2_rn(ox, oy);
    op[1] = __floats2half2_rn(oz, ow);
}

// ---------------------------------------------------------------------------
// Final fused: LayerNorm (half in, fp32 stats) + ReLU + dot(Wout) + bias
// + ReLU -> out[row].
// ---------------------------------------------------------------------------
__global__ __launch_bounds__(256)
void ln_dot_h(const __half* __restrict__ H, const float* __restrict__ g,
              const float* __restrict__ be, const float* __restrict__ Wout,
              const float* __restrict__ bout, float* __restrict__ out)
{
    const int row = blockIdx.x;
    const int tid = threadIdx.x;
    const __half2* p = (const __half2*)(H + (size_t)row * 1024) + tid * 2;
    const float2 f0 = __half22float2(p[0]);
    const float2 f1 = __half22float2(p[1]);

    float s  = f0.x + f0.y + f1.x + f1.y;
    float sq = f0.x * f0.x + f0.y * f0.y + f1.x * f1.x + f1.y * f1.y;

    __shared__ float ss[8], ssq[8];
    const int lane = tid & 31, warp = tid >> 5;
#pragma unroll
    for (int o = 16; o > 0; o >>= 1) {
        s  += __shfl_down_sync(0xffffffffu, s,  o);
        sq += __shfl_down_sync(0xffffffffu, sq, o);
    }
    if (lane == 0) { ss[warp] = s; ssq[warp] = sq; }
    __syncthreads();
    if (warp == 0) {
        s  = (lane < 8) ? ss[lane]  : 0.f;
        sq = (lane < 8) ? ssq[lane] : 0.f;
#pragma unroll
        for (int o = 4; o > 0; o >>= 1) {
            s  += __shfl_down_sync(0xffffffffu, s,  o);
            sq += __shfl_down_sync(0xffffffffu, sq, o);
        }
        if (lane == 0) { ss[0] = s; ssq[0] = sq; }
    }
    __syncthreads();

    const float mean = ss[0] * (1.0f / 1024.0f);
    const float var  = ssq[0] * (1.0f / 1024.0f) - mean * mean;
    const float rstd = rsqrtf(var + 1e-6f);

    const float4 gv = ((const float4*)g)[tid];
    const float4 bv = ((const float4*)be)[tid];
    const float4 wv = ((const float4*)Wout)[tid];
    float d = 0.f;
    d = fmaf(fmaxf(fmaf((f0.x - mean) * rstd, gv.x, bv.x), 0.f), wv.x, d);
    d = fmaf(fmaxf(fmaf((f0.y - mean) * rstd, gv.y, bv.y), 0.f), wv.y, d);
    d = fmaf(fmaxf(fmaf((f1.x - mean) * rstd, gv.z, bv.z), 0.f), wv.z, d);
    d = fmaf(fmaxf(fmaf((f1.y - mean) * rstd, gv.w, bv.w), 0.f), wv.w, d);

#pragma unroll
    for (int o = 16; o > 0; o >>= 1) d += __shfl_down_sync(0xffffffffu, d, o);
    if (lane == 0) ss[warp] = d;
    __syncthreads();
    if (tid == 0) {
        float t = 0.f;
#pragma unroll
        for (int w = 0; w < 8; w++) t += ss[w];
        out[row] = fmaxf(t + bout[0], 0.f);
    }
}

// ---------------------------------------------------------------------------
extern "C" void kernel_launch(void* const* d_in, const int* in_sizes, int n_in,
                              void* d_out, int out_size)
{
    const float* X    = (const float*)d_in[0];
    const float* W0   = (const float*)d_in[1];
    const float* b0   = (const float*)d_in[2];
    const float* W1   = (const float*)d_in[3];
    const float* g1   = (const float*)d_in[4];
    const float* be1  = (const float*)d_in[5];
    const float* W2   = (const float*)d_in[6];
    const float* g2   = (const float*)d_in[7];
    const float* be2  = (const float*)d_in[8];
    const float* W3   = (const float*)d_in[9];
    const float* g3   = (const float*)d_in[10];
    const float* be3  = (const float*)d_in[11];
    const float* Wout = (const float*)d_in[12];
    const float* bout = (const float*)d_in[13];
    float* out = (float*)d_out;

    __half *hX, *hA, *hB, *wh0, *wh1, *wh2, *wh3;
    cudaGetSymbolAddress((void**)&hX,  g_hX);
    cudaGetSymbolAddress((void**)&hA,  g_hA);
    cudaGetSymbolAddress((void**)&hB,  g_hB);
    cudaGetSymbolAddress((void**)&wh0, g_wh0);
    cudaGetSymbolAddress((void**)&wh1, g_wh1);
    cudaGetSymbolAddress((void**)&wh2, g_wh2);
    cudaGetSymbolAddress((void**)&wh3, g_wh3);

    constexpr int SMEM_REQ = 5 * 24576;   // 120 KB
    cudaFuncSetAttribute(gemm_h<D_IN, 1>,
                         cudaFuncAttributeMaxDynamicSharedMemorySize, SMEM_REQ);
    cudaFuncSetAttribute(gemm_h<HID, 0>,
                         cudaFuncAttributeMaxDynamicSharedMemorySize, SMEM_REQ);

    // prep: round X to fp16; transpose + round weights
    round_copy_h<<<(N_ROWS * D_IN) / (256 * 4), 256>>>(X, hX);
    transpose_h<<<dim3(HID / 32, D_IN / 32), dim3(32, 8)>>>(W0, wh0, D_IN, HID);
    transpose_h<<<dim3(HID / 32, HID / 32), dim3(32, 8)>>>(W1, wh1, HID, HID);
    transpose_h<<<dim3(HID / 32, HID / 32), dim3(32, 8)>>>(W2, wh2, HID, HID);
    transpose_h<<<dim3(HID / 32, HID / 32), dim3(32, 8)>>>(W3, wh3, HID, HID);

    const dim3 grid(HID / 256, N_ROWS / 128);   // (4, 512)

    // layer 0: Dense + bias + relu -> half
    gemm_h<D_IN, 1><<<grid, 512, SMEM_REQ>>>(hX, wh0, b0, hA);

    // layers 1-2: Dense -> half raw; LN(stats from half) + relu -> half
    gemm_h<HID, 0><<<grid, 512, SMEM_REQ>>>(hA, wh1, nullptr, hB);
    ln_relu_hh<<<N_ROWS, 256>>>(hB, g1, be1, hA);

    gemm_h<HID, 0><<<grid, 512, SMEM_REQ>>>(hA, wh2, nullptr, hB);
    ln_relu_hh<<<N_ROWS, 256>>>(hB, g2, be2, hA);

    // layer 3: Dense -> half raw
    gemm_h<HID, 0><<<grid, 512, SMEM_REQ>>>(hA, wh3, nullptr, hB);

    // final: LN (stats from half) + relu + Dense(1) + relu, fused
    ln_dot_h<<<N_ROWS, 256>>>(hB, g3, be3, Wout, bout, out);
}